// round 2
// baseline (speedup 1.0000x reference)
#include <cuda_runtime.h>

// MeanAggregator: ragged segment-mean with sorted segment_ids (int32 — JAX x64 off).
// out[n, :] = mean over edges e with segment_ids[e]==n of features[neighbor_idx[e], :]
// One warp per node; binary search for the edge range; coalesced float4 row reads.

#define D_FEAT 128
#define VEC_PER_ROW (D_FEAT / 4)   // 32 float4 per row -> 1 per lane

__global__ void __launch_bounds__(256)
seg_mean_kernel(const float* __restrict__ feat,
                const int* __restrict__ nbr,
                const int* __restrict__ sid,
                float* __restrict__ out,
                int n_nodes, int n_edges)
{
    const int lane = threadIdx.x & 31;
    const int warp = threadIdx.x >> 5;
    const int node = blockIdx.x * (blockDim.x >> 5) + warp;
    if (node >= n_nodes) return;

    // lower_bound / upper_bound over sorted sid. Warp-uniform -> broadcast loads.
    int lo = 0, hi = n_edges;
    while (lo < hi) {
        int mid = (lo + hi) >> 1;
        if (__ldg(&sid[mid]) < node) lo = mid + 1; else hi = mid;
    }
    const int start = lo;
    hi = n_edges;
    while (lo < hi) {
        int mid = (lo + hi) >> 1;
        if (__ldg(&sid[mid]) <= node) lo = mid + 1; else hi = mid;
    }
    const int end = lo;

    const float4* __restrict__ featv = (const float4*)feat;

    float4 acc0 = make_float4(0.f, 0.f, 0.f, 0.f);
    float4 acc1 = make_float4(0.f, 0.f, 0.f, 0.f);

    int e = start;
    // Unroll x2 with independent accumulators for memory-level parallelism.
    for (; e + 2 <= end; e += 2) {
        int i0 = __ldg(&nbr[e]);
        int i1 = __ldg(&nbr[e + 1]);
        // Clamp defensively: wrong-dtype theory then shows as rel_err, not a crash.
        i0 = min(max(i0, 0), n_nodes - 1);
        i1 = min(max(i1, 0), n_nodes - 1);
        float4 v0 = __ldg(&featv[(long long)i0 * VEC_PER_ROW + lane]);
        float4 v1 = __ldg(&featv[(long long)i1 * VEC_PER_ROW + lane]);
        acc0.x += v0.x; acc0.y += v0.y; acc0.z += v0.z; acc0.w += v0.w;
        acc1.x += v1.x; acc1.y += v1.y; acc1.z += v1.z; acc1.w += v1.w;
    }
    if (e < end) {
        int i0 = __ldg(&nbr[e]);
        i0 = min(max(i0, 0), n_nodes - 1);
        float4 v0 = __ldg(&featv[(long long)i0 * VEC_PER_ROW + lane]);
        acc0.x += v0.x; acc0.y += v0.y; acc0.z += v0.z; acc0.w += v0.w;
    }

    acc0.x += acc1.x; acc0.y += acc1.y; acc0.z += acc1.z; acc0.w += acc1.w;

    const int cnt = end - start;
    const float inv = (cnt > 0) ? (1.0f / (float)cnt) : 0.0f;
    acc0.x *= inv; acc0.y *= inv; acc0.z *= inv; acc0.w *= inv;

    ((float4*)out)[(long long)node * VEC_PER_ROW + lane] = acc0;
}

extern "C" void kernel_launch(void* const* d_in, const int* in_sizes, int n_in,
                              void* d_out, int out_size)
{
    const float* feat = (const float*)d_in[0];   // [N, 128] f32
    const int*   nbr  = (const int*)d_in[1];     // [E] i32 (JAX default int)
    const int*   sid  = (const int*)d_in[2];     // [E] i32, sorted
    float*       out  = (float*)d_out;           // [N, 128] f32

    const int n_edges = in_sizes[1];
    const int n_nodes = out_size / D_FEAT;

    const int threads = 256;                 // 8 warps -> 8 nodes per block
    const int nodes_per_block = threads / 32;
    const int blocks = (n_nodes + nodes_per_block - 1) / nodes_per_block;

    seg_mean_kernel<<<blocks, threads>>>(feat, nbr, sid, out, n_nodes, n_edges);
}

// round 3
// speedup vs baseline: 1.2186x; 1.2186x over previous
#include <cuda_runtime.h>

// MeanAggregator: ragged segment-mean with sorted int32 segment_ids.
// One warp per node. Block of 8 warps covers 8 consecutive nodes; the 9
// segment boundaries are found by 9 lanes of warp 0 (scalar binary searches)
// and shared via shmem — upper_bound(n) == lower_bound(n+1).
// Feature rows gathered as coalesced float4 (512B/row), x4 unroll for MLP.

#define D_FEAT 128
#define VEC_PER_ROW (D_FEAT / 4)   // 32 float4 per row -> 1 per lane
#define WARPS_PER_BLOCK 8

__global__ void __launch_bounds__(256)
seg_mean_kernel(const float* __restrict__ feat,
                const int* __restrict__ nbr,
                const int* __restrict__ sid,
                float* __restrict__ out,
                int n_nodes, int n_edges)
{
    __shared__ int bounds[WARPS_PER_BLOCK + 1];

    const int lane = threadIdx.x & 31;
    const int warp = threadIdx.x >> 5;
    const int node_base = blockIdx.x * WARPS_PER_BLOCK;

    // Warp 0, lanes 0..8: lower_bound(sid, node_base + lane).
    if (warp == 0 && lane <= WARPS_PER_BLOCK) {
        const int target = node_base + lane;
        int lo = 0, hi = n_edges;
        while (lo < hi) {
            int mid = (lo + hi) >> 1;
            if (__ldg(&sid[mid]) < target) lo = mid + 1; else hi = mid;
        }
        bounds[lane] = lo;
    }
    __syncthreads();

    const int node = node_base + warp;
    if (node >= n_nodes) return;

    const int start = bounds[warp];
    const int end   = bounds[warp + 1];

    const float4* __restrict__ featv = (const float4*)feat;

    float4 acc0 = make_float4(0.f, 0.f, 0.f, 0.f);
    float4 acc1 = make_float4(0.f, 0.f, 0.f, 0.f);

    int e = start;
    // x4 unroll: 4 independent feature loads in flight per warp.
    for (; e + 4 <= end; e += 4) {
        int i0 = __ldg(&nbr[e]);
        int i1 = __ldg(&nbr[e + 1]);
        int i2 = __ldg(&nbr[e + 2]);
        int i3 = __ldg(&nbr[e + 3]);
        float4 v0 = __ldg(&featv[i0 * VEC_PER_ROW + lane]);
        float4 v1 = __ldg(&featv[i1 * VEC_PER_ROW + lane]);
        float4 v2 = __ldg(&featv[i2 * VEC_PER_ROW + lane]);
        float4 v3 = __ldg(&featv[i3 * VEC_PER_ROW + lane]);
        acc0.x += v0.x; acc0.y += v0.y; acc0.z += v0.z; acc0.w += v0.w;
        acc1.x += v1.x; acc1.y += v1.y; acc1.z += v1.z; acc1.w += v1.w;
        acc0.x += v2.x; acc0.y += v2.y; acc0.z += v2.z; acc0.w += v2.w;
        acc1.x += v3.x; acc1.y += v3.y; acc1.z += v3.z; acc1.w += v3.w;
    }
    for (; e < end; e++) {
        int i0 = __ldg(&nbr[e]);
        float4 v0 = __ldg(&featv[i0 * VEC_PER_ROW + lane]);
        acc0.x += v0.x; acc0.y += v0.y; acc0.z += v0.z; acc0.w += v0.w;
    }

    acc0.x += acc1.x; acc0.y += acc1.y; acc0.z += acc1.z; acc0.w += acc1.w;

    const int cnt = end - start;
    const float inv = (cnt > 0) ? (1.0f / (float)cnt) : 0.0f;
    acc0.x *= inv; acc0.y *= inv; acc0.z *= inv; acc0.w *= inv;

    ((float4*)out)[node * VEC_PER_ROW + lane] = acc0;
}

extern "C" void kernel_launch(void* const* d_in, const int* in_sizes, int n_in,
                              void* d_out, int out_size)
{
    const float* feat = (const float*)d_in[0];   // [N, 128] f32
    const int*   nbr  = (const int*)d_in[1];     // [E] i32
    const int*   sid  = (const int*)d_in[2];     // [E] i32, sorted
    float*       out  = (float*)d_out;           // [N, 128] f32

    const int n_edges = in_sizes[1];
    const int n_nodes = out_size / D_FEAT;

    const int threads = 32 * WARPS_PER_BLOCK;
    const int blocks = (n_nodes + WARPS_PER_BLOCK - 1) / WARPS_PER_BLOCK;

    seg_mean_kernel<<<blocks, threads>>>(feat, nbr, sid, out, n_nodes, n_edges);
}